// round 15
// baseline (speedup 1.0000x reference)
#include <cuda_runtime.h>
#include <cuda_bf16.h>
#include <cstdint>

#define DEV_INLINE __device__ __forceinline__

// Problem dims (fixed): B=2, S=2048, H=2048
constexpr int TOK = 4096;
constexpr int H   = 2048;
constexpr int H4  = 8192;
constexpr int SPLITK = 4;
constexpr size_t OUT_SZ = (size_t)TOK * H;

// ---------------------------------------------------------------------------
// Scratch (device globals — no allocations allowed)
// ---------------------------------------------------------------------------
__device__ __nv_bfloat16 g_Xq [(size_t)TOK * H];   // quantized LN(x)    [4096,2048]
__device__ __nv_bfloat16 g_W1q[(size_t)H4 * H];    // quantized W1       [8192,2048]
__device__ __nv_bfloat16 g_W2q[(size_t)H * H4];    // quantized W2       [2048,8192]
__device__ __nv_bfloat16 g_H1q[(size_t)TOK * H4];  // quantized gelu out [4096,8192]
__device__ float         g_P  [SPLITK * OUT_SZ];   // split-K partials   128MB

// ---------------------------------------------------------------------------
// Helpers
// ---------------------------------------------------------------------------
DEV_INLINE float bf16r(float x) { return __bfloat162float(__float2bfloat16(x)); }

// pack two floats -> bf16x2 (lo = first arg) in one CVT
DEV_INLINE uint32_t pack_bf2(float lo, float hi) {
    uint32_t r;
    asm("cvt.rn.bf16x2.f32 %0, %1, %2;" : "=r"(r) : "f"(hi), "f"(lo));
    return r;
}

// fast tanh-gelu: gelu(x) = x * sigmoid(2c(x + 0.044715 x^3)), bf16-rounded.
// k1 = 2c*log2(e), k2 = k1*0.044715  (c = sqrt(2/pi))
DEV_INLINE float gelu_fast_bf16(float x) {
    const float k1 = 2.30220821f;
    const float k2 = 0.102943241f;
    float x2 = x * x;
    float f  = x * fmaf(k2, x2, k1);      // 2a * log2(e)
    float e;
    asm("ex2.approx.f32 %0, %1;" : "=f"(e) : "f"(f));   // e^(2a)
    float r;
    asm("rcp.approx.f32 %0, %1;" : "=f"(r) : "f"(e + 1.0f));
    return bf16r(fmaf(-x, r, x));         // x * (1 - 1/(e^(2a)+1))
}

DEV_INLINE uint32_t smem_u32(const void* p) {
    uint32_t a;
    asm("{ .reg .u64 t; cvta.to.shared.u64 t, %1; cvt.u32.u64 %0, t; }" : "=r"(a) : "l"(p));
    return a;
}

DEV_INLINE void cp16s(uint32_t dst, const void* src) {
    asm volatile("cp.async.cg.shared.global [%0], [%1], 16;\n" ::"r"(dst), "l"(src));
}

DEV_INLINE void ldsm4(uint32_t* r, uint32_t a) {
    asm volatile("ldmatrix.sync.aligned.m8n8.x4.shared.b16 {%0,%1,%2,%3}, [%4];"
                 : "=r"(r[0]), "=r"(r[1]), "=r"(r[2]), "=r"(r[3]) : "r"(a));
}

DEV_INLINE void mma16816(float* d, const uint32_t* a, uint32_t b0, uint32_t b1) {
    asm volatile(
        "mma.sync.aligned.m16n8k16.row.col.f32.bf16.bf16.f32 "
        "{%0,%1,%2,%3},{%4,%5,%6,%7},{%8,%9},{%0,%1,%2,%3};"
        : "+f"(d[0]), "+f"(d[1]), "+f"(d[2]), "+f"(d[3])
        : "r"(a[0]), "r"(a[1]), "r"(a[2]), "r"(a[3]), "r"(b0), "r"(b1));
}

#define MBAR_INIT(a, c) \
    asm volatile("mbarrier.init.shared.b64 [%0], %1;" ::"r"(a), "r"(c) : "memory")

#define MBAR_ARRIVE(a) \
    asm volatile("{.reg .b64 t; mbarrier.arrive.shared.b64 t, [%0];}" ::"r"(a) : "memory")

// .noinc is load-bearing (round 8 deadlock without it).
#define CP_MBAR_ARRIVE(a) \
    asm volatile("cp.async.mbarrier.arrive.noinc.shared.b64 [%0];" ::"r"(a) : "memory")

#define MBAR_WAIT(a, ph) do {                                                        \
    uint32_t _m = (a), _p = (ph), _d;                                                \
    asm volatile("{\n\t.reg .pred p;\n\t"                                            \
        "mbarrier.try_wait.parity.acquire.cta.shared::cta.b64 p, [%1], %2;\n\t"      \
        "selp.b32 %0, 1, 0, p;\n\t}" : "=r"(_d) : "r"(_m), "r"(_p) : "memory");      \
    if (!_d) {                                                                       \
        asm volatile("{\n\t.reg .pred P1;\n\t"                                       \
            "W_%=:\n\t"                                                              \
            "mbarrier.try_wait.parity.acquire.cta.shared::cta.b64 P1, [%0], %1, 0x989680;\n\t" \
            "@P1 bra.uni D_%=;\n\tbra.uni W_%=;\n\tD_%=:\n\t}"                       \
            :: "r"(_m), "r"(_p) : "memory");                                         \
    }                                                                                \
} while (0)

// ---------------------------------------------------------------------------
// MX quant of 8 values held by this thread; block = 4 consecutive threads.
// Writes packed bf16x2 into q[4]. Lower clamp (-128) never binds (rint>=-128).
// ---------------------------------------------------------------------------
DEV_INLINE void mx_quant8(const float* g, uint32_t* q) {
    float a = 0.0f;
#pragma unroll
    for (int j = 0; j < 8; j++) a = fmaxf(a, fabsf(g[j]));
    a = fmaxf(a, __shfl_xor_sync(0xffffffffu, a, 1));
    a = fmaxf(a, __shfl_xor_sync(0xffffffffu, a, 2));
    if (a > 0.0f) {
        float se  = floorf(log2f(a));
        float inv = exp2f(6.0f - se);
        float sc  = exp2f(se - 6.0f);
#pragma unroll
        for (int j = 0; j < 4; j++) {
            float q0 = fminf(rintf(g[2 * j + 0] * inv), 127.0f) * sc;
            float q1 = fminf(rintf(g[2 * j + 1] * inv), 127.0f) * sc;
            q[j] = pack_bf2(q0, q1);
        }
    } else {
#pragma unroll
        for (int j = 0; j < 4; j++) q[j] = 0u;
    }
}

// ---------------------------------------------------------------------------
// Prep kernel: W1 quant + LN(+quant). (W2 quant is hidden in GEMM1's prologue.)
//   CTAs [0, WCTAS)       : quantize W1 (8 contiguous elems/thread)
//   CTAs [WCTAS, +TOK)    : bf16-round + LayerNorm + bf16 + MX-quant rows
// ---------------------------------------------------------------------------
constexpr int WELEMS = H4 * H;                // 16777216 per weight
constexpr int WCTAS  = WELEMS / (256 * 8);    // 8192

__global__ __launch_bounds__(256) void prep_kernel(
    const float* __restrict__ W1,
    const float* __restrict__ x,  const float* __restrict__ lnw,
    const float* __restrict__ lnb)
{
    const int bid = blockIdx.x;
    const int tid = threadIdx.x;

    if (bid < WCTAS) {
        const size_t base = ((size_t)bid * 256 + tid) * 8;
        float4 v0 = *(const float4*)(W1 + base);
        float4 v1 = *(const float4*)(W1 + base + 4);
        float g[8] = {v0.x, v0.y, v0.z, v0.w, v1.x, v1.y, v1.z, v1.w};
        uint32_t q[4];
        mx_quant8(g, q);
        *(uint4*)(g_W1q + base) = make_uint4(q[0], q[1], q[2], q[3]);
        return;
    }

    // ---- LayerNorm + MX quant: 8 contiguous elems per thread ----
    __shared__ float red[8];
    const int row = bid - WCTAS;
    const float* xr = x + (size_t)row * H + tid * 8;

    float4 a0 = *(const float4*)(xr);
    float4 a1 = *(const float4*)(xr + 4);
    float v[8] = {bf16r(a0.x), bf16r(a0.y), bf16r(a0.z), bf16r(a0.w),
                  bf16r(a1.x), bf16r(a1.y), bf16r(a1.z), bf16r(a1.w)};

    float s = 0.0f;
#pragma unroll
    for (int j = 0; j < 8; j++) s += v[j];
#pragma unroll
    for (int o = 16; o; o >>= 1) s += __shfl_xor_sync(0xffffffffu, s, o);
    if ((tid & 31) == 0) red[tid >> 5] = s;
    __syncthreads();
    float tot = 0.0f;
#pragma unroll
    for (int i = 0; i < 8; i++) tot += red[i];
    float mu = tot * (1.0f / H);
    __syncthreads();

    float s2 = 0.0f;
#pragma unroll
    for (int j = 0; j < 8; j++) { float d = v[j] - mu; s2 += d * d; }
#pragma unroll
    for (int o = 16; o; o >>= 1) s2 += __shfl_xor_sync(0xffffffffu, s2, o);
    if ((tid & 31) == 0) red[tid >> 5] = s2;
    __syncthreads();
    float tot2 = 0.0f;
#pragma unroll
    for (int i = 0; i < 8; i++) tot2 += red[i];
    float rs = rsqrtf(tot2 * (1.0f / H) + 1e-5f);

    float4 w0 = *(const float4*)(lnw + tid * 8);
    float4 w1 = *(const float4*)(lnw + tid * 8 + 4);
    float4 b0 = *(const float4*)(lnb + tid * 8);
    float4 b1 = *(const float4*)(lnb + tid * 8 + 4);
    const float ww[8] = {w0.x, w0.y, w0.z, w0.w, w1.x, w1.y, w1.z, w1.w};
    const float bb[8] = {b0.x, b0.y, b0.z, b0.w, b1.x, b1.y, b1.z, b1.w};

    float h[8];
#pragma unroll
    for (int j = 0; j < 8; j++)
        h[j] = bf16r((v[j] - mu) * rs * ww[j] + bb[j]);

    uint32_t q[4];
    mx_quant8(h, q);
    *(uint4*)(g_Xq + (size_t)row * H + tid * 8) = make_uint4(q[0], q[1], q[2], q[3]);
}

// ---------------------------------------------------------------------------
// GEMM — round-10 configuration (best measured):
// mma.sync + ldmatrix + SW128 smem + mbarrier pipeline.
// CTA 128x256, BK=64 (K-span 2048 per CTA), 3-stage cp.async ring
// (48KB/stage, 144KB, 1 CTA/SM), 256 threads (8 warps, 2(M) x 4(N)),
// warp tile 64x64.
// PHASE 1: A=g_Xq (K=2048), B=g_W1q; PROLOGUE also quantizes this CTA's
//          16384-element slice of W2 (hidden under cp.async / mainloop BW);
//          epilogue +b1, bf16, fast-gelu, bf16, MX-quant -> g_H1q
// PHASE 2: split-K partial: A=g_H1q (this CTA covers [z*2048,(z+1)*2048)),
//          B=g_W2q; epilogue raw f32 -> g_P[z]
// ---------------------------------------------------------------------------
constexpr int BM = 128, BN = 256, BK = 64;
constexpr int NSTG = 3;
constexpr int STG = (BM + BN) * 128;       // 48 KB per stage (rows of 128B)
constexpr int SMEM_DYN = NSTG * STG;       // 144 KB

template <int PHASE>
__global__ __launch_bounds__(256, 1) void gemm_tc(const float* __restrict__ bias,
                                                  const float* __restrict__ w2src) {
    constexpr int KROW = (PHASE == 1) ? H : H4;   // row stride of A/B in elements
    constexpr int NT = 2048 / BK;                 // K-span per CTA is always 2048
    const __nv_bfloat16* __restrict__ A  = (PHASE == 1) ? g_Xq  : g_H1q;
    const __nv_bfloat16* __restrict__ Bp = (PHASE == 1) ? g_W1q : g_W2q;

    extern __shared__ __align__(128) uint8_t dyn_smem[];
    const uint32_t sbase = smem_u32(dyn_smem);
    __shared__ __align__(8) uint64_t s_full[NSTG], s_empty[NSTG];
    const uint32_t mbF = smem_u32(&s_full[0]);
    const uint32_t mbE = smem_u32(&s_empty[0]);

    const int tid  = threadIdx.x;
    const int wid  = tid >> 5;
    const int lane = tid & 31;
    const int wm   = wid & 1;      // 0..1 (M, 64 rows each)
    const int wn   = wid >> 1;     // 0..3 (N, 64 cols each)
    const int m0   = blockIdx.y * BM;
    const int n0   = blockIdx.x * BN;
    const size_t kOff = (PHASE == 1) ? 0 : (size_t)blockIdx.z * 2048;

    if (tid == 0) {
#pragma unroll
        for (int s = 0; s < NSTG; s++) {
            MBAR_INIT(mbF + s * 8, 256);
            MBAR_INIT(mbE + s * 8, 256);
        }
    }
    __syncthreads();

    // ---- cp.async loader geometry (SW128 swizzle) ----
    const int rA = tid >> 3;                           // 0..31
    const int cc = tid & 7;                            // 16B chunk within 128B row
    const uint32_t swcol = (uint32_t)(cc * 16) ^ ((uint32_t)(rA & 7) * 16);
    const __nv_bfloat16* gA = A  + (size_t)(m0 + rA) * KROW + kOff + cc * 8;
    const __nv_bfloat16* gB = Bp + (size_t)(n0 + rA) * KROW + kOff + cc * 8;
    const uint32_t sA_l = sbase + rA * 128 + swcol;
    const uint32_t sB_l = sA_l + BM * 128;

    auto load_tile = [&](int t, int s) {
        const uint32_t o = (uint32_t)s * STG;
        const __nv_bfloat16* ga = gA + t * BK;
        const __nv_bfloat16* gb = gB + t * BK;
#pragma unroll
        for (int i = 0; i < BM / 32; i++)
            cp16s(sA_l + o + i * 32 * 128, ga + (size_t)i * 32 * KROW);
#pragma unroll
        for (int i = 0; i < BN / 32; i++)
            cp16s(sB_l + o + i * 32 * 128, gb + (size_t)i * 32 * KROW);
    };

    // ---- ldmatrix fragment addressing ----
    const int lrow = lane & 7;
    const int lq   = lane >> 3;                        // 0..3
    const uint32_t swk = (uint32_t)lrow * 16;
    uint32_t aRow[4];
#pragma unroll
    for (int mt = 0; mt < 4; mt++)
        aRow[mt] = (uint32_t)(wm * 64 + mt * 16 + lrow + (lq & 1) * 8) * 128;
    const uint32_t aCol = (uint32_t)(lq >> 1) * 16;
    uint32_t bRow[4];
#pragma unroll
    for (int f = 0; f < 4; f++)
        bRow[f] = (uint32_t)(wn * 64 + f * 16 + (lq >> 1) * 8 + lrow) * 128 + BM * 128;
    const uint32_t bCol = (uint32_t)(lq & 1) * 16;

    float acc[4][8][4];
#pragma unroll
    for (int a = 0; a < 4; a++)
#pragma unroll
        for (int b = 0; b < 8; b++)
#pragma unroll
            for (int c = 0; c < 4; c++) acc[a][b][c] = 0.0f;

    // ---- prologue: tiles 0,1 into stages 0,1 ----
#pragma unroll
    for (int t = 0; t < 2; t++) {
        load_tile(t, t);
        CP_MBAR_ARRIVE(mbF + t * 8);
    }

    // ---- PHASE 1 only: quantize this CTA's W2 slice while cp.async flies ----
    if (PHASE == 1) {
        const int cid = blockIdx.y * gridDim.x + blockIdx.x;      // 0..1023
        const size_t wbase = (size_t)cid * 16384;
#pragma unroll
        for (int i = 0; i < 8; i++) {
            const size_t off = wbase + (size_t)i * 2048 + tid * 8;
            float4 v0 = *(const float4*)(w2src + off);
            float4 v1 = *(const float4*)(w2src + off + 4);
            float g[8] = {v0.x, v0.y, v0.z, v0.w, v1.x, v1.y, v1.z, v1.w};
            uint32_t q[4];
            mx_quant8(g, q);
            *(uint4*)(g_W2q + off) = make_uint4(q[0], q[1], q[2], q[3]);
        }
    }

    // ---- main loop (mbarrier-pipelined) ----
    for (int kt = 0; kt < NT; kt++) {
        const int s = kt % NSTG;

        const int lt = kt + 2;
        if (lt < NT) {
            const int sl = lt % NSTG;
            if (lt >= NSTG) MBAR_WAIT(mbE + sl * 8, ((lt - NSTG) / NSTG) & 1);
            load_tile(lt, sl);
            CP_MBAR_ARRIVE(mbF + sl * 8);
        }

        MBAR_WAIT(mbF + s * 8, (kt / NSTG) & 1);

        const uint32_t sb = sbase + (uint32_t)s * STG;

#pragma unroll
        for (int ks = 0; ks < BK / 16; ks++) {
            const uint32_t kc = (uint32_t)ks * 32;
            uint32_t af[4][4];
#pragma unroll
            for (int mt = 0; mt < 4; mt++)
                ldsm4(af[mt], sb + aRow[mt] + ((kc + aCol) ^ swk));
#pragma unroll
            for (int f = 0; f < 4; f++) {
                uint32_t bq[4];
                ldsm4(bq, sb + bRow[f] + ((kc + bCol) ^ swk));
#pragma unroll
                for (int hf = 0; hf < 2; hf++)
#pragma unroll
                    for (int mt = 0; mt < 4; mt++)
                        mma16816(acc[mt][f * 2 + hf], af[mt],
                                 bq[hf * 2], bq[hf * 2 + 1]);
            }
        }

        MBAR_ARRIVE(mbE + s * 8);
    }

    // ---- epilogue ----
    const int gr = lane >> 2;          // row within 8
    const int gc = (lane & 3) * 2;     // col pair within 8

    if (PHASE == 1) {
#pragma unroll
        for (int mt = 0; mt < 4; mt++) {
#pragma unroll
            for (int c2 = 0; c2 < 2; c2++) {
                const int m = m0 + wm * 64 + mt * 16 + c2 * 8 + gr;
#pragma unroll
                for (int h = 0; h < 2; h++) {
                    float g[8];
                    float amax = 0.0f;
#pragma unroll
                    for (int j = 0; j < 4; j++) {
                        const int nt = 4 * h + j;
                        const int c  = n0 + wn * 64 + h * 32 + j * 8 + gc;
                        const float2 bb = __ldg((const float2*)(bias + c));
                        float y0 = acc[mt][nt][c2 * 2 + 0] + bb.x;
                        float y1 = acc[mt][nt][c2 * 2 + 1] + bb.y;
                        g[2 * j + 0] = gelu_fast_bf16(bf16r(y0));
                        g[2 * j + 1] = gelu_fast_bf16(bf16r(y1));
                        amax = fmaxf(amax, fmaxf(fabsf(g[2 * j]), fabsf(g[2 * j + 1])));
                    }
                    amax = fmaxf(amax, __shfl_xor_sync(0xffffffffu, amax, 1));
                    amax = fmaxf(amax, __shfl_xor_sync(0xffffffffu, amax, 2));
                    uint32_t q[4];
                    if (amax > 0.0f) {
                        float se  = floorf(log2f(amax));
                        float inv = exp2f(6.0f - se);
                        float sc  = exp2f(se - 6.0f);
#pragma unroll
                        for (int j = 0; j < 4; j++) {
                            float q0 = fminf(rintf(g[2 * j + 0] * inv), 127.0f) * sc;
                            float q1 = fminf(rintf(g[2 * j + 1] * inv), 127.0f) * sc;
                            q[j] = pack_bf2(q0, q1);
                        }
                    } else {
#pragma unroll
                        for (int j = 0; j < 4; j++) q[j] = 0u;
                    }
#pragma unroll
                    for (int j = 0; j < 4; j++) {
                        const int c = n0 + wn * 64 + h * 32 + j * 8 + gc;
                        *(uint32_t*)(&g_H1q[(size_t)m * H4 + c]) = q[j];
                    }
                }
            }
        }
    } else {
        float* P = g_P + (size_t)blockIdx.z * OUT_SZ;
#pragma unroll
        for (int mt = 0; mt < 4; mt++) {
#pragma unroll
            for (int c2 = 0; c2 < 2; c2++) {
                const int m = m0 + wm * 64 + mt * 16 + c2 * 8 + gr;
#pragma unroll
                for (int nt = 0; nt < 8; nt++) {
                    const int c = n0 + wn * 64 + nt * 8 + gc;
                    *(float2*)(&P[(size_t)m * H + c]) =
                        make_float2(acc[mt][nt][c2 * 2 + 0], acc[mt][nt][c2 * 2 + 1]);
                }
            }
        }
    }
}

// ---------------------------------------------------------------------------
// Split-K reduction + final epilogue: out = bf16(bf16(resid) + bf16(sum+b2))
// ---------------------------------------------------------------------------
__global__ __launch_bounds__(256) void reduce_out_kernel(const float* __restrict__ b2,
                                                         const float* __restrict__ resid,
                                                         float* __restrict__ outf) {
    size_t i = ((size_t)blockIdx.x * 256 + threadIdx.x) * 4;
    float4 p0 = *(const float4*)(g_P + i);
    float4 p1 = *(const float4*)(g_P + OUT_SZ + i);
    float4 p2 = *(const float4*)(g_P + 2 * OUT_SZ + i);
    float4 p3 = *(const float4*)(g_P + 3 * OUT_SZ + i);
    const float4 bb = __ldg((const float4*)(b2 + (i & (H - 1))));
    const float4 rv = *(const float4*)(resid + i);
    float4 ov;
    ov.x = bf16r(bf16r(rv.x) + bf16r(((p0.x + p1.x) + p2.x) + p3.x + bb.x));
    ov.y = bf16r(bf16r(rv.y) + bf16r(((p0.y + p1.y) + p2.y) + p3.y + bb.y));
    ov.z = bf16r(bf16r(rv.z) + bf16r(((p0.z + p1.z) + p2.z) + p3.z + bb.z));
    ov.w = bf16r(bf16r(rv.w) + bf16r(((p0.w + p1.w) + p2.w) + p3.w + bb.w));
    *(float4*)(outf + i) = ov;
}

// ---------------------------------------------------------------------------
// Launch
// ---------------------------------------------------------------------------
extern "C" void kernel_launch(void* const* d_in, const int* in_sizes, int n_in,
                              void* d_out, int out_size) {
    const float* inputs = (const float*)d_in[0];
    const float* ln_w   = (const float*)d_in[1];
    const float* ln_b   = (const float*)d_in[2];
    const float* W1     = (const float*)d_in[3];
    const float* b1     = (const float*)d_in[4];
    const float* W2     = (const float*)d_in[5];
    const float* b2     = (const float*)d_in[6];
    float* out = (float*)d_out;

    cudaFuncSetAttribute(gemm_tc<1>, cudaFuncAttributeMaxDynamicSharedMemorySize, SMEM_DYN);
    cudaFuncSetAttribute(gemm_tc<2>, cudaFuncAttributeMaxDynamicSharedMemorySize, SMEM_DYN);

    // prep: W1 quant + LN/quant (W2 quant hidden inside GEMM1's prologue)
    prep_kernel<<<WCTAS + TOK, 256>>>(W1, inputs, ln_w, ln_b);

    // GEMM1 (+W2 quant in prologue): -> gelu+quant -> g_H1q  (32x32 CTAs)
    gemm_tc<1><<<dim3(H4 / BN, TOK / BM), 256, SMEM_DYN>>>(b1, W2);

    // GEMM2 split-K=4: partials to g_P  (8x32x4 CTAs)
    gemm_tc<2><<<dim3(H / BN, TOK / BM, SPLITK), 256, SMEM_DYN>>>(nullptr, nullptr);

    // reduce + bias + residual -> out
    reduce_out_kernel<<<(int)(OUT_SZ / (256 * 4)), 256>>>(b2, inputs, out);
}

// round 16
// speedup vs baseline: 1.0131x; 1.0131x over previous
#include <cuda_runtime.h>
#include <cuda_bf16.h>
#include <cstdint>

#define DEV_INLINE __device__ __forceinline__

// Problem dims (fixed): B=2, S=2048, H=2048
constexpr int TOK = 4096;
constexpr int H   = 2048;
constexpr int H4  = 8192;
constexpr int SPLITK = 4;
constexpr size_t OUT_SZ = (size_t)TOK * H;

// ---------------------------------------------------------------------------
// Scratch (device globals — no allocations allowed)
// ---------------------------------------------------------------------------
__device__ __nv_bfloat16 g_Xq [(size_t)TOK * H];   // quantized LN(x)    [4096,2048]
__device__ __nv_bfloat16 g_W1q[(size_t)H4 * H];    // quantized W1       [8192,2048]
__device__ __nv_bfloat16 g_W2q[(size_t)H * H4];    // quantized W2       [2048,8192]
__device__ __nv_bfloat16 g_H1q[(size_t)TOK * H4];  // quantized gelu out [4096,8192]
__device__ float         g_P  [SPLITK * OUT_SZ];   // split-K partials   128MB

// ---------------------------------------------------------------------------
// Helpers
// ---------------------------------------------------------------------------
DEV_INLINE float bf16r(float x) { return __bfloat162float(__float2bfloat16(x)); }

// pack two floats -> bf16x2 (lo = first arg) in one CVT
DEV_INLINE uint32_t pack_bf2(float lo, float hi) {
    uint32_t r;
    asm("cvt.rn.bf16x2.f32 %0, %1, %2;" : "=r"(r) : "f"(hi), "f"(lo));
    return r;
}

// fast tanh-gelu: gelu(x) = x * sigmoid(2c(x + 0.044715 x^3)), bf16-rounded.
// k1 = 2c*log2(e), k2 = k1*0.044715  (c = sqrt(2/pi))
DEV_INLINE float gelu_fast_bf16(float x) {
    const float k1 = 2.30220821f;
    const float k2 = 0.102943241f;
    float x2 = x * x;
    float f  = x * fmaf(k2, x2, k1);      // 2a * log2(e)
    float e;
    asm("ex2.approx.f32 %0, %1;" : "=f"(e) : "f"(f));   // e^(2a)
    float r;
    asm("rcp.approx.f32 %0, %1;" : "=f"(r) : "f"(e + 1.0f));
    return bf16r(fmaf(-x, r, x));         // x * (1 - 1/(e^(2a)+1))
}

DEV_INLINE uint32_t smem_u32(const void* p) {
    uint32_t a;
    asm("{ .reg .u64 t; cvta.to.shared.u64 t, %1; cvt.u32.u64 %0, t; }" : "=r"(a) : "l"(p));
    return a;
}

DEV_INLINE void cp16s(uint32_t dst, const void* src) {
    asm volatile("cp.async.cg.shared.global [%0], [%1], 16;\n" ::"r"(dst), "l"(src));
}

DEV_INLINE void ldsm4(uint32_t* r, uint32_t a) {
    asm volatile("ldmatrix.sync.aligned.m8n8.x4.shared.b16 {%0,%1,%2,%3}, [%4];"
                 : "=r"(r[0]), "=r"(r[1]), "=r"(r[2]), "=r"(r[3]) : "r"(a));
}

DEV_INLINE void mma16816(float* d, const uint32_t* a, uint32_t b0, uint32_t b1) {
    asm volatile(
        "mma.sync.aligned.m16n8k16.row.col.f32.bf16.bf16.f32 "
        "{%0,%1,%2,%3},{%4,%5,%6,%7},{%8,%9},{%0,%1,%2,%3};"
        : "+f"(d[0]), "+f"(d[1]), "+f"(d[2]), "+f"(d[3])
        : "r"(a[0]), "r"(a[1]), "r"(a[2]), "r"(a[3]), "r"(b0), "r"(b1));
}

#define MBAR_INIT(a, c) \
    asm volatile("mbarrier.init.shared.b64 [%0], %1;" ::"r"(a), "r"(c) : "memory")

#define MBAR_ARRIVE(a) \
    asm volatile("{.reg .b64 t; mbarrier.arrive.shared.b64 t, [%0];}" ::"r"(a) : "memory")

// .noinc is load-bearing (round 8 deadlock without it).
#define CP_MBAR_ARRIVE(a) \
    asm volatile("cp.async.mbarrier.arrive.noinc.shared.b64 [%0];" ::"r"(a) : "memory")

#define MBAR_WAIT(a, ph) do {                                                        \
    uint32_t _m = (a), _p = (ph), _d;                                                \
    asm volatile("{\n\t.reg .pred p;\n\t"                                            \
        "mbarrier.try_wait.parity.acquire.cta.shared::cta.b64 p, [%1], %2;\n\t"      \
        "selp.b32 %0, 1, 0, p;\n\t}" : "=r"(_d) : "r"(_m), "r"(_p) : "memory");      \
    if (!_d) {                                                                       \
        asm volatile("{\n\t.reg .pred P1;\n\t"                                       \
            "W_%=:\n\t"                                                              \
            "mbarrier.try_wait.parity.acquire.cta.shared::cta.b64 P1, [%0], %1, 0x989680;\n\t" \
            "@P1 bra.uni D_%=;\n\tbra.uni W_%=;\n\tD_%=:\n\t}"                       \
            :: "r"(_m), "r"(_p) : "memory");                                         \
    }                                                                                \
} while (0)

// ---------------------------------------------------------------------------
// MX quant of 8 values held by this thread; block = 4 consecutive threads.
// Writes packed bf16x2 into q[4]. Lower clamp (-128) never binds (rint>=-128).
// ---------------------------------------------------------------------------
DEV_INLINE void mx_quant8(const float* g, uint32_t* q) {
    float a = 0.0f;
#pragma unroll
    for (int j = 0; j < 8; j++) a = fmaxf(a, fabsf(g[j]));
    a = fmaxf(a, __shfl_xor_sync(0xffffffffu, a, 1));
    a = fmaxf(a, __shfl_xor_sync(0xffffffffu, a, 2));
    if (a > 0.0f) {
        float se  = floorf(log2f(a));
        float inv = exp2f(6.0f - se);
        float sc  = exp2f(se - 6.0f);
#pragma unroll
        for (int j = 0; j < 4; j++) {
            float q0 = fminf(rintf(g[2 * j + 0] * inv), 127.0f) * sc;
            float q1 = fminf(rintf(g[2 * j + 1] * inv), 127.0f) * sc;
            q[j] = pack_bf2(q0, q1);
        }
    } else {
#pragma unroll
        for (int j = 0; j < 4; j++) q[j] = 0u;
    }
}

// ---------------------------------------------------------------------------
// Fused prep kernel (round-14 structure): W1 quant + W2 quant + LN(+quant).
//   CTAs [0, WCTAS)          : quantize W1 (8 contiguous elems/thread)
//   CTAs [WCTAS, 2*WCTAS)    : quantize W2
//   CTAs [2*WCTAS, +TOK)     : bf16-round + LayerNorm + bf16 + MX-quant rows
// ---------------------------------------------------------------------------
constexpr int WELEMS = H4 * H;                // 16777216 per weight
constexpr int WCTAS  = WELEMS / (256 * 8);    // 8192

__global__ __launch_bounds__(256) void prep_kernel(
    const float* __restrict__ W1, const float* __restrict__ W2,
    const float* __restrict__ x,  const float* __restrict__ lnw,
    const float* __restrict__ lnb)
{
    const int bid = blockIdx.x;
    const int tid = threadIdx.x;

    if (bid < 2 * WCTAS) {
        const bool isW2 = bid >= WCTAS;
        const float* __restrict__ src = isW2 ? W2 : W1;
        __nv_bfloat16* __restrict__ dst = isW2 ? g_W2q : g_W1q;
        const size_t base = ((size_t)(isW2 ? bid - WCTAS : bid) * 256 + tid) * 8;

        float4 v0 = *(const float4*)(src + base);
        float4 v1 = *(const float4*)(src + base + 4);
        float g[8] = {v0.x, v0.y, v0.z, v0.w, v1.x, v1.y, v1.z, v1.w};
        uint32_t q[4];
        mx_quant8(g, q);
        *(uint4*)(dst + base) = make_uint4(q[0], q[1], q[2], q[3]);
        return;
    }

    // ---- LayerNorm + MX quant: 8 contiguous elems per thread ----
    __shared__ float red[8];
    const int row = bid - 2 * WCTAS;
    const float* xr = x + (size_t)row * H + tid * 8;

    float4 a0 = *(const float4*)(xr);
    float4 a1 = *(const float4*)(xr + 4);
    float v[8] = {bf16r(a0.x), bf16r(a0.y), bf16r(a0.z), bf16r(a0.w),
                  bf16r(a1.x), bf16r(a1.y), bf16r(a1.z), bf16r(a1.w)};

    float s = 0.0f;
#pragma unroll
    for (int j = 0; j < 8; j++) s += v[j];
#pragma unroll
    for (int o = 16; o; o >>= 1) s += __shfl_xor_sync(0xffffffffu, s, o);
    if ((tid & 31) == 0) red[tid >> 5] = s;
    __syncthreads();
    float tot = 0.0f;
#pragma unroll
    for (int i = 0; i < 8; i++) tot += red[i];
    float mu = tot * (1.0f / H);
    __syncthreads();

    float s2 = 0.0f;
#pragma unroll
    for (int j = 0; j < 8; j++) { float d = v[j] - mu; s2 += d * d; }
#pragma unroll
    for (int o = 16; o; o >>= 1) s2 += __shfl_xor_sync(0xffffffffu, s2, o);
    if ((tid & 31) == 0) red[tid >> 5] = s2;
    __syncthreads();
    float tot2 = 0.0f;
#pragma unroll
    for (int i = 0; i < 8; i++) tot2 += red[i];
    float rs = rsqrtf(tot2 * (1.0f / H) + 1e-5f);

    float4 w0 = *(const float4*)(lnw + tid * 8);
    float4 w1 = *(const float4*)(lnw + tid * 8 + 4);
    float4 b0 = *(const float4*)(lnb + tid * 8);
    float4 b1 = *(const float4*)(lnb + tid * 8 + 4);
    const float ww[8] = {w0.x, w0.y, w0.z, w0.w, w1.x, w1.y, w1.z, w1.w};
    const float bb[8] = {b0.x, b0.y, b0.z, b0.w, b1.x, b1.y, b1.z, b1.w};

    float h[8];
#pragma unroll
    for (int j = 0; j < 8; j++)
        h[j] = bf16r((v[j] - mu) * rs * ww[j] + bb[j]);

    uint32_t q[4];
    mx_quant8(h, q);
    *(uint4*)(g_Xq + (size_t)row * H + tid * 8) = make_uint4(q[0], q[1], q[2], q[3]);
}

// ---------------------------------------------------------------------------
// GEMM — mma.sync + ldmatrix + SW128 smem + mbarrier pipeline.
// CTA 128x256, BK=128 per stage (two BK=64 sub-tiles), NSTG=2 (96KB/stage,
// 192KB, 1 CTA/SM), 256 threads (8 warps, 2(M) x 4(N)), warp tile 64x64.
// Half the sync frequency of the BK=64/NSTG=3 version.
// PHASE 1: A=g_Xq (K=2048), B=g_W1q; epilogue +b1, bf16, fast-gelu, bf16,
//          MX-quant -> g_H1q
// PHASE 2: split-K partial: A=g_H1q (this CTA covers [z*2048,(z+1)*2048)),
//          B=g_W2q; epilogue raw f32 -> g_P[z]
// ---------------------------------------------------------------------------
constexpr int BM = 128, BN = 256, BK = 128;
constexpr int NSTG = 2;
constexpr int SUB = (BM + BN) * 128;       // 48 KB per BK=64 sub-tile
constexpr int STG2 = 2 * SUB;              // 96 KB per BK=128 stage
constexpr int SMEM_DYN = NSTG * STG2;      // 192 KB

template <int PHASE>
__global__ __launch_bounds__(256, 1) void gemm_tc(const float* __restrict__ bias) {
    constexpr int KROW = (PHASE == 1) ? H : H4;   // row stride of A/B in elements
    constexpr int NT = 2048 / BK;                 // 16 tiles per CTA
    const __nv_bfloat16* __restrict__ A  = (PHASE == 1) ? g_Xq  : g_H1q;
    const __nv_bfloat16* __restrict__ Bp = (PHASE == 1) ? g_W1q : g_W2q;

    extern __shared__ __align__(128) uint8_t dyn_smem[];
    const uint32_t sbase = smem_u32(dyn_smem);
    __shared__ __align__(8) uint64_t s_full[NSTG], s_empty[NSTG];
    const uint32_t mbF = smem_u32(&s_full[0]);
    const uint32_t mbE = smem_u32(&s_empty[0]);

    const int tid  = threadIdx.x;
    const int wid  = tid >> 5;
    const int lane = tid & 31;
    const int wm   = wid & 1;      // 0..1 (M, 64 rows each)
    const int wn   = wid >> 1;     // 0..3 (N, 64 cols each)
    const int m0   = blockIdx.y * BM;
    const int n0   = blockIdx.x * BN;
    const size_t kOff = (PHASE == 1) ? 0 : (size_t)blockIdx.z * 2048;

    if (tid == 0) {
#pragma unroll
        for (int s = 0; s < NSTG; s++) {
            MBAR_INIT(mbF + s * 8, 256);
            MBAR_INIT(mbE + s * 8, 256);
        }
    }
    __syncthreads();

    // ---- cp.async loader geometry (SW128 swizzle per 128B row) ----
    const int rA = tid >> 3;                           // 0..31
    const int cc = tid & 7;                            // 16B chunk within 128B row
    const uint32_t swcol = (uint32_t)(cc * 16) ^ ((uint32_t)(rA & 7) * 16);
    const __nv_bfloat16* gA = A  + (size_t)(m0 + rA) * KROW + kOff + cc * 8;
    const __nv_bfloat16* gB = Bp + (size_t)(n0 + rA) * KROW + kOff + cc * 8;
    const uint32_t sA_l = sbase + rA * 128 + swcol;
    const uint32_t sB_l = sA_l + BM * 128;

    // one BK=128 tile = two BK=64 sub-tiles, contiguous in the stage
    auto load_tile = [&](int t, int s) {
#pragma unroll
        for (int hh = 0; hh < 2; hh++) {
            const uint32_t o = (uint32_t)s * STG2 + (uint32_t)hh * SUB;
            const __nv_bfloat16* ga = gA + t * BK + hh * 64;
            const __nv_bfloat16* gb = gB + t * BK + hh * 64;
#pragma unroll
            for (int i = 0; i < BM / 32; i++)
                cp16s(sA_l + o + i * 32 * 128, ga + (size_t)i * 32 * KROW);
#pragma unroll
            for (int i = 0; i < BN / 32; i++)
                cp16s(sB_l + o + i * 32 * 128, gb + (size_t)i * 32 * KROW);
        }
    };

    // ---- ldmatrix fragment addressing ----
    const int lrow = lane & 7;
    const int lq   = lane >> 3;                        // 0..3
    const uint32_t swk = (uint32_t)lrow * 16;
    uint32_t aRow[4];
#pragma unroll
    for (int mt = 0; mt < 4; mt++)
        aRow[mt] = (uint32_t)(wm * 64 + mt * 16 + lrow + (lq & 1) * 8) * 128;
    const uint32_t aCol = (uint32_t)(lq >> 1) * 16;
    uint32_t bRow[4];
#pragma unroll
    for (int f = 0; f < 4; f++)
        bRow[f] = (uint32_t)(wn * 64 + f * 16 + (lq >> 1) * 8 + lrow) * 128 + BM * 128;
    const uint32_t bCol = (uint32_t)(lq & 1) * 16;

    float acc[4][8][4];
#pragma unroll
    for (int a = 0; a < 4; a++)
#pragma unroll
        for (int b = 0; b < 8; b++)
#pragma unroll
            for (int c = 0; c < 4; c++) acc[a][b][c] = 0.0f;

    // ---- prologue: tile 0 into stage 0 (lookahead = 1) ----
    load_tile(0, 0);
    CP_MBAR_ARRIVE(mbF + 0 * 8);

    // ---- main loop (mbarrier-pipelined, NSTG=2) ----
    for (int kt = 0; kt < NT; kt++) {
        const int s = kt & 1;

        const int lt = kt + 1;
        if (lt < NT) {
            const int sl = lt & 1;
            if (lt >= NSTG) MBAR_WAIT(mbE + sl * 8, ((lt - NSTG) / NSTG) & 1);
            load_tile(lt, sl);
            CP_MBAR_ARRIVE(mbF + sl * 8);
        }

        MBAR_WAIT(mbF + s * 8, (kt / NSTG) & 1);

#pragma unroll
        for (int hh = 0; hh < 2; hh++) {
            const uint32_t sb = sbase + (uint32_t)s * STG2 + (uint32_t)hh * SUB;
#pragma unroll
            for (int ks = 0; ks < 4; ks++) {
                const uint32_t kc = (uint32_t)ks * 32;
                uint32_t af[4][4];
#pragma unroll
                for (int mt = 0; mt < 4; mt++)
                    ldsm4(af[mt], sb + aRow[mt] + ((kc + aCol) ^ swk));
#pragma unroll
                for (int f = 0; f < 4; f++) {
                    uint32_t bq[4];
                    ldsm4(bq, sb + bRow[f] + ((kc + bCol) ^ swk));
#pragma unroll
                    for (int hf = 0; hf < 2; hf++)
#pragma unroll
                        for (int mt = 0; mt < 4; mt++)
                            mma16816(acc[mt][f * 2 + hf], af[mt],
                                     bq[hf * 2], bq[hf * 2 + 1]);
                }
            }
        }

        MBAR_ARRIVE(mbE + s * 8);
    }

    // ---- epilogue ----
    const int gr = lane >> 2;          // row within 8
    const int gc = (lane & 3) * 2;     // col pair within 8

    if (PHASE == 1) {
#pragma unroll
        for (int mt = 0; mt < 4; mt++) {
#pragma unroll
            for (int c2 = 0; c2 < 2; c2++) {
                const int m = m0 + wm * 64 + mt * 16 + c2 * 8 + gr;
#pragma unroll
                for (int h = 0; h < 2; h++) {
                    float g[8];
                    float amax = 0.0f;
#pragma unroll
                    for (int j = 0; j < 4; j++) {
                        const int nt = 4 * h + j;
                        const int c  = n0 + wn * 64 + h * 32 + j * 8 + gc;
                        const float2 bb = __ldg((const float2*)(bias + c));
                        float y0 = acc[mt][nt][c2 * 2 + 0] + bb.x;
                        float y1 = acc[mt][nt][c2 * 2 + 1] + bb.y;
                        g[2 * j + 0] = gelu_fast_bf16(bf16r(y0));
                        g[2 * j + 1] = gelu_fast_bf16(bf16r(y1));
                        amax = fmaxf(amax, fmaxf(fabsf(g[2 * j]), fabsf(g[2 * j + 1])));
                    }
                    amax = fmaxf(amax, __shfl_xor_sync(0xffffffffu, amax, 1));
                    amax = fmaxf(amax, __shfl_xor_sync(0xffffffffu, amax, 2));
                    uint32_t q[4];
                    if (amax > 0.0f) {
                        float se  = floorf(log2f(amax));
                        float inv = exp2f(6.0f - se);
                        float sc  = exp2f(se - 6.0f);
#pragma unroll
                        for (int j = 0; j < 4; j++) {
                            float q0 = fminf(rintf(g[2 * j + 0] * inv), 127.0f) * sc;
                            float q1 = fminf(rintf(g[2 * j + 1] * inv), 127.0f) * sc;
                            q[j] = pack_bf2(q0, q1);
                        }
                    } else {
#pragma unroll
                        for (int j = 0; j < 4; j++) q[j] = 0u;
                    }
#pragma unroll
                    for (int j = 0; j < 4; j++) {
                        const int c = n0 + wn * 64 + h * 32 + j * 8 + gc;
                        *(uint32_t*)(&g_H1q[(size_t)m * H4 + c]) = q[j];
                    }
                }
            }
        }
    } else {
        float* P = g_P + (size_t)blockIdx.z * OUT_SZ;
#pragma unroll
        for (int mt = 0; mt < 4; mt++) {
#pragma unroll
            for (int c2 = 0; c2 < 2; c2++) {
                const int m = m0 + wm * 64 + mt * 16 + c2 * 8 + gr;
#pragma unroll
                for (int nt = 0; nt < 8; nt++) {
                    const int c = n0 + wn * 64 + nt * 8 + gc;
                    *(float2*)(&P[(size_t)m * H + c]) =
                        make_float2(acc[mt][nt][c2 * 2 + 0], acc[mt][nt][c2 * 2 + 1]);
                }
            }
        }
    }
}

// ---------------------------------------------------------------------------
// Split-K reduction + final epilogue: out = bf16(bf16(resid) + bf16(sum+b2))
// ---------------------------------------------------------------------------
__global__ __launch_bounds__(256) void reduce_out_kernel(const float* __restrict__ b2,
                                                         const float* __restrict__ resid,
                                                         float* __restrict__ outf) {
    size_t i = ((size_t)blockIdx.x * 256 + threadIdx.x) * 4;
    float4 p0 = *(const float4*)(g_P + i);
    float4 p1 = *(const float4*)(g_P + OUT_SZ + i);
    float4 p2 = *(const float4*)(g_P + 2 * OUT_SZ + i);
    float4 p3 = *(const float4*)(g_P + 3 * OUT_SZ + i);
    const float4 bb = __ldg((const float4*)(b2 + (i & (H - 1))));
    const float4 rv = *(const float4*)(resid + i);
    float4 ov;
    ov.x = bf16r(bf16r(rv.x) + bf16r(((p0.x + p1.x) + p2.x) + p3.x + bb.x));
    ov.y = bf16r(bf16r(rv.y) + bf16r(((p0.y + p1.y) + p2.y) + p3.y + bb.y));
    ov.z = bf16r(bf16r(rv.z) + bf16r(((p0.z + p1.z) + p2.z) + p3.z + bb.z));
    ov.w = bf16r(bf16r(rv.w) + bf16r(((p0.w + p1.w) + p2.w) + p3.w + bb.w));
    *(float4*)(outf + i) = ov;
}

// ---------------------------------------------------------------------------
// Launch
// ---------------------------------------------------------------------------
extern "C" void kernel_launch(void* const* d_in, const int* in_sizes, int n_in,
                              void* d_out, int out_size) {
    const float* inputs = (const float*)d_in[0];
    const float* ln_w   = (const float*)d_in[1];
    const float* ln_b   = (const float*)d_in[2];
    const float* W1     = (const float*)d_in[3];
    const float* b1     = (const float*)d_in[4];
    const float* W2     = (const float*)d_in[5];
    const float* b2     = (const float*)d_in[6];
    float* out = (float*)d_out;

    cudaFuncSetAttribute(gemm_tc<1>, cudaFuncAttributeMaxDynamicSharedMemorySize, SMEM_DYN);
    cudaFuncSetAttribute(gemm_tc<2>, cudaFuncAttributeMaxDynamicSharedMemorySize, SMEM_DYN);

    // fused: W1 quant + W2 quant + LN/quant in one launch
    prep_kernel<<<2 * WCTAS + TOK, 256>>>(W1, W2, inputs, ln_w, ln_b);

    // GEMM1: [4096,2048] x [8192,2048]^T -> gelu+quant -> g_H1q  (32x32 CTAs)
    gemm_tc<1><<<dim3(H4 / BN, TOK / BM), 256, SMEM_DYN>>>(b1);

    // GEMM2 split-K=4: partials to g_P  (8x32x4 CTAs)
    gemm_tc<2><<<dim3(H / BN, TOK / BM, SPLITK), 256, SMEM_DYN>>>(nullptr);

    // reduce + bias + residual -> out
    reduce_out_kernel<<<(int)(OUT_SZ / (256 * 4)), 256>>>(b2, inputs, out);
}